// round 4
// baseline (speedup 1.0000x reference)
#include <cuda_runtime.h>
#include <cuda_bf16.h>
#include <math.h>
#include <stdint.h>

#define N_NODES 100000
#define N_EDGES 1600000
#define HID 128
#define BN_EPS 1e-5f

// ---------------- device scratch (allocation-free, referenced only from device code) ----------------
__device__ __align__(16) float g_h[(size_t)N_NODES * HID];   // 51.2 MB (layer activations)
__device__ __align__(16) float g_p[(size_t)N_NODES * HID];   // 51.2 MB (p = h@wl)  -- gather target
__device__ __align__(16) float g_q[(size_t)N_NODES * HID];   // 51.2 MB (q = h@wr)
__device__ int   g_rowptr[N_NODES + 1];
__device__ int   g_cursor[N_NODES];
__device__ int   g_srcs[N_EDGES];

// ---------------- CSR build ----------------
__global__ void k_zero_deg() {
    int i = blockIdx.x * blockDim.x + threadIdx.x;
    if (i < N_NODES) g_cursor[i] = 0;
}

// edge_index int32 on device: [2, E] row-major. src = ei[e], dst = ei[N_EDGES + e].
__global__ void k_hist(const int* __restrict__ ei) {
    int e = blockIdx.x * blockDim.x + threadIdx.x;
    if (e < N_EDGES) {
        int dst = ei[N_EDGES + e];
        if (dst >= 0 && dst < N_NODES)
            atomicAdd(&g_cursor[dst], 1);
    }
}

__global__ void k_scan() {
    __shared__ int sums[1024];
    const int CH = (N_NODES + 1023) / 1024;
    int t = threadIdx.x;
    int lo = t * CH;
    int hi = min(lo + CH, N_NODES);
    int s = 0;
    for (int i = lo; i < hi; ++i) s += g_cursor[i];
    sums[t] = s;
    __syncthreads();
    for (int off = 1; off < 1024; off <<= 1) {
        int v = (t >= off) ? sums[t - off] : 0;
        __syncthreads();
        sums[t] += v;
        __syncthreads();
    }
    int run = (t == 0) ? 0 : sums[t - 1];
    for (int i = lo; i < hi; ++i) {
        int d = g_cursor[i];
        g_rowptr[i] = run;
        run += d;
    }
    if (t == 1023) g_rowptr[N_NODES] = sums[1023];
}

__global__ void k_cursor_init() {
    int i = blockIdx.x * blockDim.x + threadIdx.x;
    if (i < N_NODES) g_cursor[i] = g_rowptr[i];
}

__global__ void k_place(const int* __restrict__ ei) {
    int e = blockIdx.x * blockDim.x + threadIdx.x;
    if (e < N_EDGES) {
        int src = ei[e];
        int dst = ei[N_EDGES + e];
        if (dst >= 0 && dst < N_NODES && src >= 0 && src < N_NODES) {
            int pos = atomicAdd(&g_cursor[dst], 1);
            if (pos >= 0 && pos < N_EDGES) g_srcs[pos] = src;
        }
    }
}

// ---------------- GEMM with packed f32x2 FMAs ----------------
// out = A @ W,  A:[N,K] row-major (layer0 ? X : g_h),  W:[K,128],  out = blockIdx.y ? g_q : g_p.
// 128x128 tile, 256 threads, 8x8 per thread; accumulators paired along columns.
__global__ __launch_bounds__(256, 2) void k_gemm(const float* __restrict__ X, int K,
                                                 const float* __restrict__ Wl,
                                                 const float* __restrict__ Wr,
                                                 int layer0) {
    __shared__ float As[16][136];   // transposed A tile, padded
    __shared__ float Bs[16][128];

    const float* __restrict__ A = layer0 ? X : (const float*)g_h;
    float* __restrict__ out = blockIdx.y ? g_q : g_p;
    const float* __restrict__ B = blockIdx.y ? Wr : Wl;
    const int m0 = blockIdx.x * 128;

    int t = threadIdx.x;
    int tx = t & 15;        // 8 output cols each
    int ty = t >> 4;        // 8 output rows each
    int ar = t >> 2;        // A tile row
    int ac = (t & 3) * 4;   // A tile k offset
    int br = t >> 5;        // B tile k row
    int bc = (t & 31) * 4;  // B tile col

    // acc2[i][j] = packed (col tx*8+2j, tx*8+2j+1) for row ty*8+i
    uint64_t acc2[8][4];
#pragma unroll
    for (int i = 0; i < 8; ++i)
#pragma unroll
        for (int j = 0; j < 4; ++j) acc2[i][j] = 0ull;

    for (int k0 = 0; k0 < K; k0 += 16) {
#pragma unroll
        for (int half = 0; half < 2; ++half) {
            int row = m0 + ar + half * 64;
            float4 v = make_float4(0.f, 0.f, 0.f, 0.f);
            if (row < N_NODES)
                v = *(const float4*)(A + (size_t)row * K + k0 + ac);
            As[ac + 0][ar + half * 64] = v.x;
            As[ac + 1][ar + half * 64] = v.y;
            As[ac + 2][ar + half * 64] = v.z;
            As[ac + 3][ar + half * 64] = v.w;
        }
#pragma unroll
        for (int half = 0; half < 2; ++half) {
            int kk = k0 + br + half * 8;
            float4 v = *(const float4*)(B + (size_t)kk * 128 + bc);
            *(float4*)&Bs[br + half * 8][bc] = v;
        }
        __syncthreads();

#pragma unroll
        for (int k = 0; k < 16; ++k) {
            float a[8];
            *(float4*)(a)     = *(const float4*)&As[k][ty * 8];
            *(float4*)(a + 4) = *(const float4*)&As[k][ty * 8 + 4];
            uint64_t b2[4];
            b2[0] = *(const uint64_t*)&Bs[k][tx * 8 + 0];
            b2[1] = *(const uint64_t*)&Bs[k][tx * 8 + 2];
            b2[2] = *(const uint64_t*)&Bs[k][tx * 8 + 4];
            b2[3] = *(const uint64_t*)&Bs[k][tx * 8 + 6];
#pragma unroll
            for (int i = 0; i < 8; ++i) {
                uint64_t ap;
                asm("mov.b64 %0, {%1, %1};" : "=l"(ap) : "r"(__float_as_uint(a[i])));
#pragma unroll
                for (int j = 0; j < 4; ++j)
                    asm("fma.rn.f32x2 %0, %1, %2, %0;"
                        : "+l"(acc2[i][j]) : "l"(ap), "l"(b2[j]));
            }
        }
        __syncthreads();
    }

    int colbase = tx * 8;
#pragma unroll
    for (int i = 0; i < 8; ++i) {
        int row = m0 + ty * 8 + i;
        if (row < N_NODES) {
            float* o = out + (size_t)row * 128 + colbase;
            *(uint64_t*)(o + 0) = acc2[i][0];
            *(uint64_t*)(o + 2) = acc2[i][1];
            *(uint64_t*)(o + 4) = acc2[i][2];
            *(uint64_t*)(o + 6) = acc2[i][3];
        }
    }
}

// ---------------- fused aggregation + bias + BN + ReLU (+ optional final head) ----------------
// h_tmp = relu( BN( mean_{e: dst=i} p[src_e] + q[i] + bl ) )
// if last: out[i] = h_tmp . lin_w + lin_b   else: g_h[i] = h_tmp
__global__ __launch_bounds__(256) void k_agg(const float* __restrict__ bl,
                                             const float* __restrict__ gam,
                                             const float* __restrict__ bet,
                                             const float* __restrict__ rm,
                                             const float* __restrict__ rv,
                                             const float* __restrict__ lin_w,
                                             const float* __restrict__ lin_b,
                                             float* __restrict__ out,
                                             int last) {
    int node = (blockIdx.x * blockDim.x + threadIdx.x) >> 5;
    if (node >= N_NODES) return;
    int lane = threadIdx.x & 31;
    int c = lane * 4;

    int s0 = g_rowptr[node];
    int s1 = g_rowptr[node + 1];
    float4 acc = make_float4(0.f, 0.f, 0.f, 0.f);
    for (int e = s0; e < s1; ++e) {
        int s = g_srcs[e];
        float4 v = *(const float4*)(g_p + (size_t)s * HID + c);
        acc.x += v.x; acc.y += v.y; acc.z += v.z; acc.w += v.w;
    }
    float inv = 1.f / (float)max(s1 - s0, 1);

    float4 q   = *(const float4*)(g_q + (size_t)node * HID + c);
    float4 vb  = *(const float4*)(bl + c);
    float4 vg  = *(const float4*)(gam + c);
    float4 vbe = *(const float4*)(bet + c);
    float4 vrm = *(const float4*)(rm + c);
    float4 vrv = *(const float4*)(rv + c);

    float o0 = acc.x * inv + q.x + vb.x;
    float o1 = acc.y * inv + q.y + vb.y;
    float o2 = acc.z * inv + q.z + vb.z;
    float o3 = acc.w * inv + q.w + vb.w;

    o0 = (o0 - vrm.x) * (vg.x * rsqrtf(vrv.x + BN_EPS)) + vbe.x;
    o1 = (o1 - vrm.y) * (vg.y * rsqrtf(vrv.y + BN_EPS)) + vbe.y;
    o2 = (o2 - vrm.z) * (vg.z * rsqrtf(vrv.z + BN_EPS)) + vbe.z;
    o3 = (o3 - vrm.w) * (vg.w * rsqrtf(vrv.w + BN_EPS)) + vbe.w;

    o0 = fmaxf(o0, 0.f); o1 = fmaxf(o1, 0.f);
    o2 = fmaxf(o2, 0.f); o3 = fmaxf(o3, 0.f);

    if (last) {
        float4 wv = *(const float4*)(lin_w + c);
        float s = o0 * wv.x + o1 * wv.y + o2 * wv.z + o3 * wv.w;
#pragma unroll
        for (int off = 16; off > 0; off >>= 1)
            s += __shfl_down_sync(0xffffffffu, s, off);
        if (lane == 0) out[node] = s + lin_b[0];
    } else {
        float4 r; r.x = o0; r.y = o1; r.z = o2; r.w = o3;
        *(float4*)(g_h + (size_t)node * HID + c) = r;
    }
}

// ---------------- launch ----------------
extern "C" void kernel_launch(void* const* d_in, const int* in_sizes, int n_in,
                              void* d_out, int out_size) {
    const float* x  = (const float*)d_in[0];
    const int*   ei = (const int*)d_in[1];
    const float* wl[3]; const float* wr[3]; const float* bl[3];
    const float* gm[3]; const float* be[3]; const float* rm[3]; const float* rv[3];
    for (int i = 0; i < 3; ++i) {
        const int base = 2 + 7 * i;
        wl[i] = (const float*)d_in[base + 0];
        wr[i] = (const float*)d_in[base + 1];
        bl[i] = (const float*)d_in[base + 2];
        gm[i] = (const float*)d_in[base + 3];
        be[i] = (const float*)d_in[base + 4];
        rm[i] = (const float*)d_in[base + 5];
        rv[i] = (const float*)d_in[base + 6];
    }
    const float* lin_w = (const float*)d_in[23];
    const float* lin_b = (const float*)d_in[24];
    float* out = (float*)d_out;

    const int TB = 256;
    const int nb_nodes = (N_NODES + TB - 1) / TB;
    const int nb_edges = (N_EDGES + TB - 1) / TB;
    const int nb_warps = (N_NODES * 32 + TB - 1) / TB;

    // CSR build
    k_zero_deg<<<nb_nodes, TB>>>();
    k_hist<<<nb_edges, TB>>>(ei);
    k_scan<<<1, 1024>>>();
    k_cursor_init<<<nb_nodes, TB>>>();
    k_place<<<nb_edges, TB>>>(ei);

    // 3 SAGE layers
    dim3 ggrid((N_NODES + 127) / 128, 2);
    k_gemm<<<ggrid, 256>>>(x, 160, wl[0], wr[0], 1);
    k_agg<<<nb_warps, TB>>>(bl[0], gm[0], be[0], rm[0], rv[0], lin_w, lin_b, out, 0);
    k_gemm<<<ggrid, 256>>>(x, 128, wl[1], wr[1], 0);
    k_agg<<<nb_warps, TB>>>(bl[1], gm[1], be[1], rm[1], rv[1], lin_w, lin_b, out, 0);
    k_gemm<<<ggrid, 256>>>(x, 128, wl[2], wr[2], 0);
    k_agg<<<nb_warps, TB>>>(bl[2], gm[2], be[2], rm[2], rv[2], lin_w, lin_b, out, 1);
}

// round 6
// speedup vs baseline: 1.3139x; 1.3139x over previous
#include <cuda_runtime.h>
#include <cuda_bf16.h>
#include <math.h>
#include <stdint.h>

#define N_NODES 100000
#define N_EDGES 1600000
#define HID 128
#define BN_EPS 1e-5f
#define N_TILES ((N_NODES + 127) / 128)   // 782

// ---------------- device scratch ----------------
__device__ __align__(16) float g_p[(size_t)N_NODES * HID];   // p = h@wl  (gather target)
__device__ __align__(16) float g_q[(size_t)N_NODES * HID];   // q = h@wr
__device__ __align__(16) __nv_bfloat16 g_ahi[(size_t)N_NODES * 192];  // activation hi
__device__ __align__(16) __nv_bfloat16 g_alo[(size_t)N_NODES * 192];  // activation lo
__device__ __align__(16) __nv_bfloat16 g_bhi[256 * 192];     // weight^T hi  [n][k]
__device__ __align__(16) __nv_bfloat16 g_blo[256 * 192];     // weight^T lo
__device__ int g_rowptr[N_NODES + 1];
__device__ int g_cursor[N_NODES];
__device__ int g_srcs[N_EDGES];

static __device__ __forceinline__ uint32_t sw128(uint32_t b) { return b ^ ((b >> 3) & 0x70u); }
__device__ __forceinline__ uint32_t smem_to_u32(const void* p) {
    uint32_t a;
    asm("{ .reg .u64 t; cvta.to.shared.u64 t, %1; cvt.u32.u64 %0, t; }" : "=r"(a) : "l"(p));
    return a;
}

// ---------------- CSR build ----------------
__global__ void k_zero_deg() {
    int i = blockIdx.x * blockDim.x + threadIdx.x;
    if (i < N_NODES) g_cursor[i] = 0;
}
__global__ void k_hist(const int* __restrict__ ei) {
    int e = blockIdx.x * blockDim.x + threadIdx.x;
    if (e < N_EDGES) {
        int dst = ei[N_EDGES + e];
        if (dst >= 0 && dst < N_NODES) atomicAdd(&g_cursor[dst], 1);
    }
}
__global__ void k_scan() {
    __shared__ int sums[1024];
    const int CH = (N_NODES + 1023) / 1024;
    int t = threadIdx.x;
    int lo = t * CH, hi = min(lo + CH, N_NODES);
    int s = 0;
    for (int i = lo; i < hi; ++i) s += g_cursor[i];
    sums[t] = s;
    __syncthreads();
    for (int off = 1; off < 1024; off <<= 1) {
        int v = (t >= off) ? sums[t - off] : 0;
        __syncthreads();
        sums[t] += v;
        __syncthreads();
    }
    int run = (t == 0) ? 0 : sums[t - 1];
    for (int i = lo; i < hi; ++i) {
        int d = g_cursor[i];
        g_rowptr[i] = run;
        run += d;
    }
    if (t == 1023) g_rowptr[N_NODES] = sums[1023];
}
__global__ void k_cursor_init() {
    int i = blockIdx.x * blockDim.x + threadIdx.x;
    if (i < N_NODES) g_cursor[i] = g_rowptr[i];
}
__global__ void k_place(const int* __restrict__ ei) {
    int e = blockIdx.x * blockDim.x + threadIdx.x;
    if (e < N_EDGES) {
        int src = ei[e];
        int dst = ei[N_EDGES + e];
        if (dst >= 0 && dst < N_NODES && src >= 0 && src < N_NODES) {
            int pos = atomicAdd(&g_cursor[dst], 1);
            if (pos >= 0 && pos < N_EDGES) g_srcs[pos] = src;
        }
    }
}

// ---------------- bf16 hi/lo split ----------------
__device__ __forceinline__ void split2(float f0, float f1, uint32_t& hp, uint32_t& lp) {
    asm("cvt.rn.bf16x2.f32 %0, %1, %2;" : "=r"(hp) : "f"(f1), "f"(f0));
    float h0 = __uint_as_float(hp << 16);
    float h1 = __uint_as_float(hp & 0xFFFF0000u);
    float l0 = f0 - h0, l1 = f1 - h1;
    asm("cvt.rn.bf16x2.f32 %0, %1, %2;" : "=r"(lp) : "f"(l1), "f"(l0));
}

// ---------------- prepass: x (fp32, K=160) -> g_ahi/g_alo (stride 192, zero-padded) ----------------
__global__ void k_prep_x(const float* __restrict__ x) {
    int idx = blockIdx.x * blockDim.x + threadIdx.x;
    if (idx >= N_NODES * 48) return;
    int row = idx / 48;
    int c = (idx % 48) * 4;
    float4 v = make_float4(0.f, 0.f, 0.f, 0.f);
    if (c < 160) v = *(const float4*)(x + (size_t)row * 160 + c);
    uint32_t h0, l0, h1, l1;
    split2(v.x, v.y, h0, l0);
    split2(v.z, v.w, h1, l1);
    uint32_t* ph = (uint32_t*)((char*)g_ahi + ((size_t)row * 192 + c) * 2);
    uint32_t* pl = (uint32_t*)((char*)g_alo + ((size_t)row * 192 + c) * 2);
    ph[0] = h0; ph[1] = h1;
    pl[0] = l0; pl[1] = l1;
}

// ---------------- prepass: weights [K,128]x2 -> g_bhi/g_blo transposed [256 x Kpad] ----------------
__global__ void k_prep_w(const float* __restrict__ wl, const float* __restrict__ wr,
                         int K, int Kpad) {
    int idx = blockIdx.x * blockDim.x + threadIdx.x;
    int total = 256 * (Kpad / 4);
    if (idx >= total) return;
    int n = idx / (Kpad / 4);
    int k = (idx % (Kpad / 4)) * 4;
    const float* W = (n < 128) ? wl : wr;
    int nc = n & 127;
    float f[4];
#pragma unroll
    for (int j = 0; j < 4; ++j)
        f[j] = (k + j < K) ? W[(size_t)(k + j) * 128 + nc] : 0.f;
    uint32_t h0, l0, h1, l1;
    split2(f[0], f[1], h0, l0);
    split2(f[2], f[3], h1, l1);
    uint32_t* ph = (uint32_t*)((char*)g_bhi + ((size_t)n * Kpad + k) * 2);
    uint32_t* pl = (uint32_t*)((char*)g_blo + ((size_t)n * Kpad + k) * 2);
    ph[0] = h0; ph[1] = h1;
    pl[0] = l0; pl[1] = l1;
}

// ---------------- tensor GEMM via mma.sync (sm_80-compatible): [g_p|g_q] = A @ B^T, 3-term bf16 split ----------------
// CTA: 128 rows x 128 cols (blockIdx.y: 0 -> wl half/g_p, 1 -> wr half/g_q). 8 warps in 2(m) x 4(n).
__global__ __launch_bounds__(256, 2) void k_mma(int stride, int nkc) {
    __shared__ __align__(1024) char sm[32768];   // As 128x64 bf16 (16KB) | Bs 128x64 bf16 (16KB)
    const uint32_t As = smem_to_u32(sm);
    const uint32_t Bs = As + 16384;

    const int tid = threadIdx.x;
    const int lane = tid & 31;
    const int wid = tid >> 5;
    const int wm = wid & 1;          // m-strip: wm*64
    const int wn = wid >> 1;         // n-strip: wn*32
    const int m0 = blockIdx.x * 128;
    const int nsel = blockIdx.y;

    float acc[4][4][4];
#pragma unroll
    for (int i = 0; i < 4; ++i)
#pragma unroll
        for (int j = 0; j < 4; ++j)
#pragma unroll
            for (int r = 0; r < 4; ++r) acc[i][j][r] = 0.f;

    // per-lane ldmatrix row/col components (k-chunk-invariant parts)
    const int a_row = wm * 64 + ((lane >> 3) & 1) * 8 + (lane & 7);  // + mt*16
    const int a_c16 = lane >> 4;                                     // + ks*2
    const int b_row = wn * 32 + (lane & 7);                          // + nt*8
    const int b_c16 = (lane >> 3) & 1;                               // + ks*2

    for (int t = 0; t < 3; ++t) {
        const char* Aarr = (const char*)((t < 2) ? g_ahi : g_alo);
        const char* Barr = (const char*)((t == 1) ? g_blo : g_bhi);
        for (int kc = 0; kc < nkc; ++kc) {
            const int k0 = kc * 64;
            // stage A chunk: 128 rows x 64 bf16, SW128
#pragma unroll
            for (int it = 0; it < 4; ++it) {
                int idx = tid + it * 256;
                int row = idx >> 3, c16 = idx & 7;
                int grow = m0 + row;
                uint4 v = make_uint4(0, 0, 0, 0);
                if (grow < N_NODES)
                    v = *(const uint4*)(Aarr + ((size_t)grow * stride + k0) * 2 + c16 * 16);
                *(uint4*)(sm + sw128(row * 128 + c16 * 16)) = v;
            }
            // stage B chunk: 128 n-rows x 64 bf16, SW128
#pragma unroll
            for (int it = 0; it < 4; ++it) {
                int idx = tid + it * 256;
                int row = idx >> 3, c16 = idx & 7;
                uint4 v = *(const uint4*)(Barr + ((size_t)(nsel * 128 + row) * stride + k0) * 2 + c16 * 16);
                *(uint4*)(sm + 16384 + sw128(row * 128 + c16 * 16)) = v;
            }
            __syncthreads();

#pragma unroll
            for (int ks = 0; ks < 4; ++ks) {
                // A fragments: 4 m-tiles
                uint32_t af[4][4];
#pragma unroll
                for (int mt = 0; mt < 4; ++mt) {
                    uint32_t addr = As + sw128((uint32_t)(a_row + mt * 16) * 128 +
                                               (uint32_t)(a_c16 + ks * 2) * 16);
                    asm volatile("ldmatrix.sync.aligned.m8n8.x4.shared.b16 {%0,%1,%2,%3}, [%4];"
                                 : "=r"(af[mt][0]), "=r"(af[mt][1]), "=r"(af[mt][2]), "=r"(af[mt][3])
                                 : "r"(addr));
                }
                // B fragments: 4 n-tiles
                uint32_t bf[4][2];
#pragma unroll
                for (int nt = 0; nt < 4; ++nt) {
                    uint32_t addr = Bs + sw128((uint32_t)(b_row + nt * 8) * 128 +
                                               (uint32_t)(b_c16 + ks * 2) * 16);
                    asm volatile("ldmatrix.sync.aligned.m8n8.x2.shared.b16 {%0,%1}, [%2];"
                                 : "=r"(bf[nt][0]), "=r"(bf[nt][1])
                                 : "r"(addr));
                }
#pragma unroll
                for (int mt = 0; mt < 4; ++mt)
#pragma unroll
                    for (int nt = 0; nt < 4; ++nt)
                        asm volatile(
                            "mma.sync.aligned.m16n8k16.row.col.f32.bf16.bf16.f32 "
                            "{%0,%1,%2,%3}, {%4,%5,%6,%7}, {%8,%9}, {%0,%1,%2,%3};"
                            : "+f"(acc[mt][nt][0]), "+f"(acc[mt][nt][1]),
                              "+f"(acc[mt][nt][2]), "+f"(acc[mt][nt][3])
                            : "r"(af[mt][0]), "r"(af[mt][1]), "r"(af[mt][2]), "r"(af[mt][3]),
                              "r"(bf[nt][0]), "r"(bf[nt][1]));
            }
            __syncthreads();
        }
    }

    // epilogue: direct stores
    float* __restrict__ out = nsel ? g_q : g_p;
    const int colb = wn * 32 + (lane & 3) * 2;
    const int rowb = m0 + wm * 64 + (lane >> 2);
#pragma unroll
    for (int mt = 0; mt < 4; ++mt) {
        int r0 = rowb + mt * 16;
        int r1 = r0 + 8;
#pragma unroll
        for (int nt = 0; nt < 4; ++nt) {
            int col = colb + nt * 8;
            if (r0 < N_NODES) {
                float2 v; v.x = acc[mt][nt][0]; v.y = acc[mt][nt][1];
                *(float2*)(out + (size_t)r0 * HID + col) = v;
            }
            if (r1 < N_NODES) {
                float2 v; v.x = acc[mt][nt][2]; v.y = acc[mt][nt][3];
                *(float2*)(out + (size_t)r1 * HID + col) = v;
            }
        }
    }
}

// ---------------- fused aggregation + bias + BN + ReLU (+ hi/lo split or final head) ----------------
__global__ __launch_bounds__(256) void k_agg(const float* __restrict__ bl,
                                             const float* __restrict__ gam,
                                             const float* __restrict__ bet,
                                             const float* __restrict__ rm,
                                             const float* __restrict__ rv,
                                             const float* __restrict__ lin_w,
                                             const float* __restrict__ lin_b,
                                             float* __restrict__ out,
                                             int last) {
    int node = (blockIdx.x * blockDim.x + threadIdx.x) >> 5;
    if (node >= N_NODES) return;
    int lane = threadIdx.x & 31;
    int c = lane * 4;

    int s0 = g_rowptr[node];
    int s1 = g_rowptr[node + 1];
    float4 acc = make_float4(0.f, 0.f, 0.f, 0.f);
    for (int e = s0; e < s1; ++e) {
        int s = g_srcs[e];
        float4 v = *(const float4*)(g_p + (size_t)s * HID + c);
        acc.x += v.x; acc.y += v.y; acc.z += v.z; acc.w += v.w;
    }
    float inv = 1.f / (float)max(s1 - s0, 1);

    float4 q   = *(const float4*)(g_q + (size_t)node * HID + c);
    float4 vb  = *(const float4*)(bl + c);
    float4 vg  = *(const float4*)(gam + c);
    float4 vbe = *(const float4*)(bet + c);
    float4 vrm = *(const float4*)(rm + c);
    float4 vrv = *(const float4*)(rv + c);

    float o0 = acc.x * inv + q.x + vb.x;
    float o1 = acc.y * inv + q.y + vb.y;
    float o2 = acc.z * inv + q.z + vb.z;
    float o3 = acc.w * inv + q.w + vb.w;

    o0 = (o0 - vrm.x) * (vg.x * rsqrtf(vrv.x + BN_EPS)) + vbe.x;
    o1 = (o1 - vrm.y) * (vg.y * rsqrtf(vrv.y + BN_EPS)) + vbe.y;
    o2 = (o2 - vrm.z) * (vg.z * rsqrtf(vrv.z + BN_EPS)) + vbe.z;
    o3 = (o3 - vrm.w) * (vg.w * rsqrtf(vrv.w + BN_EPS)) + vbe.w;

    o0 = fmaxf(o0, 0.f); o1 = fmaxf(o1, 0.f);
    o2 = fmaxf(o2, 0.f); o3 = fmaxf(o3, 0.f);

    if (last) {
        float4 wv = *(const float4*)(lin_w + c);
        float s = o0 * wv.x + o1 * wv.y + o2 * wv.z + o3 * wv.w;
#pragma unroll
        for (int off = 16; off > 0; off >>= 1)
            s += __shfl_down_sync(0xffffffffu, s, off);
        if (lane == 0) out[node] = s + lin_b[0];
    } else {
        uint32_t h0, l0, h1, l1;
        split2(o0, o1, h0, l0);
        split2(o2, o3, h1, l1);
        uint2 hv; hv.x = h0; hv.y = h1;
        uint2 lv; lv.x = l0; lv.y = l1;
        *(uint2*)((char*)g_ahi + ((size_t)node * 128 + c) * 2) = hv;
        *(uint2*)((char*)g_alo + ((size_t)node * 128 + c) * 2) = lv;
    }
}

// ---------------- launch ----------------
extern "C" void kernel_launch(void* const* d_in, const int* in_sizes, int n_in,
                              void* d_out, int out_size) {
    const float* x  = (const float*)d_in[0];
    const int*   ei = (const int*)d_in[1];
    const float* wl[3]; const float* wr[3]; const float* bl[3];
    const float* gm[3]; const float* be[3]; const float* rm[3]; const float* rv[3];
    for (int i = 0; i < 3; ++i) {
        const int base = 2 + 7 * i;
        wl[i] = (const float*)d_in[base + 0];
        wr[i] = (const float*)d_in[base + 1];
        bl[i] = (const float*)d_in[base + 2];
        gm[i] = (const float*)d_in[base + 3];
        be[i] = (const float*)d_in[base + 4];
        rm[i] = (const float*)d_in[base + 5];
        rv[i] = (const float*)d_in[base + 6];
    }
    const float* lin_w = (const float*)d_in[23];
    const float* lin_b = (const float*)d_in[24];
    float* out = (float*)d_out;

    const int TB = 256;
    const int nb_nodes = (N_NODES + TB - 1) / TB;
    const int nb_edges = (N_EDGES + TB - 1) / TB;
    const int nb_warps = (N_NODES * 32 + TB - 1) / TB;

    // CSR build
    k_zero_deg<<<nb_nodes, TB>>>();
    k_hist<<<nb_edges, TB>>>(ei);
    k_scan<<<1, 1024>>>();
    k_cursor_init<<<nb_nodes, TB>>>();
    k_place<<<nb_edges, TB>>>(ei);

    dim3 ggrid(N_TILES, 2);
    // layer 0 (K=160, pad 192)
    k_prep_x<<<(N_NODES * 48 + TB - 1) / TB, TB>>>(x);
    k_prep_w<<<(256 * 48 + TB - 1) / TB, TB>>>(wl[0], wr[0], 160, 192);
    k_mma<<<ggrid, 256>>>(192, 3);
    k_agg<<<nb_warps, TB>>>(bl[0], gm[0], be[0], rm[0], rv[0], lin_w, lin_b, out, 0);
    // layer 1 (K=128)
    k_prep_w<<<(256 * 32 + TB - 1) / TB, TB>>>(wl[1], wr[1], 128, 128);
    k_mma<<<ggrid, 256>>>(128, 2);
    k_agg<<<nb_warps, TB>>>(bl[1], gm[1], be[1], rm[1], rv[1], lin_w, lin_b, out, 0);
    // layer 2 (K=128)
    k_prep_w<<<(256 * 32 + TB - 1) / TB, TB>>>(wl[2], wr[2], 128, 128);
    k_mma<<<ggrid, 256>>>(128, 2);
    k_agg<<<nb_warps, TB>>>(bl[2], gm[2], be[2], rm[2], rv[2], lin_w, lin_b, out, 1);
}

// round 7
// speedup vs baseline: 1.7497x; 1.3317x over previous
#include <cuda_runtime.h>
#include <cuda_bf16.h>
#include <math.h>
#include <stdint.h>

#define N_NODES 100000
#define N_EDGES 1600000
#define HID 128
#define BN_EPS 1e-5f
#define N_TILES ((N_NODES + 127) / 128)   // 782

// ---------------- device scratch ----------------
__device__ __align__(16) float g_p[(size_t)N_NODES * HID];   // p = h@wl  (gather target)
__device__ __align__(16) float g_q[(size_t)N_NODES * HID];   // q = h@wr
__device__ __align__(16) __nv_bfloat16 g_ahi[(size_t)N_NODES * 192];  // activation hi
__device__ __align__(16) __nv_bfloat16 g_alo[(size_t)N_NODES * 192];  // activation lo
__device__ __align__(16) __nv_bfloat16 g_bhi[256 * 192];     // weight^T hi  [n][k]
__device__ __align__(16) __nv_bfloat16 g_blo[256 * 192];     // weight^T lo
__device__ int g_rowptr[N_NODES + 1];
__device__ int g_cursor[N_NODES];
__device__ int g_srcs[N_EDGES];

static __device__ __forceinline__ uint32_t sw128(uint32_t b) { return b ^ ((b >> 3) & 0x70u); }
__device__ __forceinline__ uint32_t smem_to_u32(const void* p) {
    uint32_t a;
    asm("{ .reg .u64 t; cvta.to.shared.u64 t, %1; cvt.u32.u64 %0, t; }" : "=r"(a) : "l"(p));
    return a;
}

// ---------------- CSR build ----------------
__global__ void k_zero_deg() {
    int i = blockIdx.x * blockDim.x + threadIdx.x;
    if (i < N_NODES) g_cursor[i] = 0;
}
__global__ void k_hist(const int* __restrict__ ei) {
    int e = blockIdx.x * blockDim.x + threadIdx.x;
    if (e < N_EDGES) {
        int dst = ei[N_EDGES + e];
        if (dst >= 0 && dst < N_NODES) atomicAdd(&g_cursor[dst], 1);
    }
}
__global__ void k_scan() {
    __shared__ int sums[1024];
    const int CH = (N_NODES + 1023) / 1024;
    int t = threadIdx.x;
    int lo = t * CH, hi = min(lo + CH, N_NODES);
    int s = 0;
    for (int i = lo; i < hi; ++i) s += g_cursor[i];
    sums[t] = s;
    __syncthreads();
    for (int off = 1; off < 1024; off <<= 1) {
        int v = (t >= off) ? sums[t - off] : 0;
        __syncthreads();
        sums[t] += v;
        __syncthreads();
    }
    int run = (t == 0) ? 0 : sums[t - 1];
    for (int i = lo; i < hi; ++i) {
        int d = g_cursor[i];
        g_rowptr[i] = run;
        run += d;
    }
    if (t == 1023) g_rowptr[N_NODES] = sums[1023];
}
__global__ void k_cursor_init() {
    int i = blockIdx.x * blockDim.x + threadIdx.x;
    if (i < N_NODES) g_cursor[i] = g_rowptr[i];
}
__global__ void k_place(const int* __restrict__ ei) {
    int e = blockIdx.x * blockDim.x + threadIdx.x;
    if (e < N_EDGES) {
        int src = ei[e];
        int dst = ei[N_EDGES + e];
        if (dst >= 0 && dst < N_NODES && src >= 0 && src < N_NODES) {
            int pos = atomicAdd(&g_cursor[dst], 1);
            if (pos >= 0 && pos < N_EDGES) g_srcs[pos] = src;
        }
    }
}

// ---------------- bf16 hi/lo split ----------------
__device__ __forceinline__ void split2(float f0, float f1, uint32_t& hp, uint32_t& lp) {
    asm("cvt.rn.bf16x2.f32 %0, %1, %2;" : "=r"(hp) : "f"(f1), "f"(f0));
    float h0 = __uint_as_float(hp << 16);
    float h1 = __uint_as_float(hp & 0xFFFF0000u);
    float l0 = f0 - h0, l1 = f1 - h1;
    asm("cvt.rn.bf16x2.f32 %0, %1, %2;" : "=r"(lp) : "f"(l1), "f"(l0));
}

// ---------------- prepass: x (fp32, K=160) -> g_ahi/g_alo (stride 192, zero-padded) ----------------
__global__ void k_prep_x(const float* __restrict__ x) {
    int idx = blockIdx.x * blockDim.x + threadIdx.x;
    if (idx >= N_NODES * 48) return;
    int row = idx / 48;
    int c = (idx % 48) * 4;
    float4 v = make_float4(0.f, 0.f, 0.f, 0.f);
    if (c < 160) v = *(const float4*)(x + (size_t)row * 160 + c);
    uint32_t h0, l0, h1, l1;
    split2(v.x, v.y, h0, l0);
    split2(v.z, v.w, h1, l1);
    uint32_t* ph = (uint32_t*)((char*)g_ahi + ((size_t)row * 192 + c) * 2);
    uint32_t* pl = (uint32_t*)((char*)g_alo + ((size_t)row * 192 + c) * 2);
    ph[0] = h0; ph[1] = h1;
    pl[0] = l0; pl[1] = l1;
}

// ---------------- prepass: weights [K,128]x2 -> g_bhi/g_blo transposed [256 x Kpad] ----------------
__global__ void k_prep_w(const float* __restrict__ wl, const float* __restrict__ wr,
                         int K, int Kpad) {
    int idx = blockIdx.x * blockDim.x + threadIdx.x;
    int total = 256 * (Kpad / 4);
    if (idx >= total) return;
    int n = idx / (Kpad / 4);
    int k = (idx % (Kpad / 4)) * 4;
    const float* W = (n < 128) ? wl : wr;
    int nc = n & 127;
    float f[4];
#pragma unroll
    for (int j = 0; j < 4; ++j)
        f[j] = (k + j < K) ? W[(size_t)(k + j) * 128 + nc] : 0.f;
    uint32_t h0, l0, h1, l1;
    split2(f[0], f[1], h0, l0);
    split2(f[2], f[3], h1, l1);
    uint32_t* ph = (uint32_t*)((char*)g_bhi + ((size_t)n * Kpad + k) * 2);
    uint32_t* pl = (uint32_t*)((char*)g_blo + ((size_t)n * Kpad + k) * 2);
    ph[0] = h0; ph[1] = h1;
    pl[0] = l0; pl[1] = l1;
}

// ---------------- tensor GEMM via mma.sync, cp.async double-buffered pipeline ----------------
// CTA: 128 rows x 128 cols (blockIdx.y: 0 -> wl half/g_p, 1 -> wr half/g_q). 8 warps 2(m) x 4(n).
// Chunks: ci in [0, 3*nkc): term t = ci/nkc, k-chunk kc = ci%nkc. Buffers: 2 x (16KB A + 16KB B).
__global__ __launch_bounds__(256, 2) void k_mma(int stride, int nkc) {
    extern __shared__ __align__(1024) char sm[];
    const uint32_t smb = smem_to_u32(sm);

    const int tid = threadIdx.x;
    const int lane = tid & 31;
    const int wid = tid >> 5;
    const int wm = wid & 1;
    const int wn = wid >> 1;
    const int m0 = blockIdx.x * 128;
    const int nsel = blockIdx.y;
    const int total = 3 * nkc;

    float acc[4][4][4];
#pragma unroll
    for (int i = 0; i < 4; ++i)
#pragma unroll
        for (int j = 0; j < 4; ++j)
#pragma unroll
            for (int r = 0; r < 4; ++r) acc[i][j][r] = 0.f;

    const int a_row = wm * 64 + ((lane >> 3) & 1) * 8 + (lane & 7);
    const int a_c16 = lane >> 4;
    const int b_row = wn * 32 + (lane & 7);
    const int b_c16 = (lane >> 3) & 1;

    // stage chunk ci into buffer buf via cp.async
    auto stage = [&](int ci, int buf) {
        int t = ci / nkc;
        int kc = ci - t * nkc;
        const char* Aarr = (const char*)((t < 2) ? g_ahi : g_alo);
        const char* Barr = (const char*)((t == 1) ? g_blo : g_bhi);
        int k0 = kc * 64;
        uint32_t Ab = smb + buf * 32768;
        uint32_t Bb = Ab + 16384;
#pragma unroll
        for (int it = 0; it < 4; ++it) {
            int idx = tid + it * 256;
            int row = idx >> 3, c16 = idx & 7;
            int grow = m0 + row;
            const char* src = Aarr + ((size_t)grow * stride + k0) * 2 + c16 * 16;
            uint32_t dst = Ab + sw128(row * 128 + c16 * 16);
            int zf = (grow < N_NODES) ? 16 : 0;
            asm volatile("cp.async.cg.shared.global [%0], [%1], 16, %2;"
                         :: "r"(dst), "l"(src), "r"(zf));
        }
#pragma unroll
        for (int it = 0; it < 4; ++it) {
            int idx = tid + it * 256;
            int row = idx >> 3, c16 = idx & 7;
            const char* src = Barr + ((size_t)(nsel * 128 + row) * stride + k0) * 2 + c16 * 16;
            uint32_t dst = Bb + sw128(row * 128 + c16 * 16);
            asm volatile("cp.async.cg.shared.global [%0], [%1], 16;"
                         :: "r"(dst), "l"(src));
        }
        asm volatile("cp.async.commit_group;" ::: "memory");
    };

    stage(0, 0);
    for (int ci = 0; ci < total; ++ci) {
        int cb = ci & 1;
        if (ci + 1 < total) {
            stage(ci + 1, cb ^ 1);
            asm volatile("cp.async.wait_group 1;" ::: "memory");
        } else {
            asm volatile("cp.async.wait_group 0;" ::: "memory");
        }
        __syncthreads();

        const uint32_t As = smb + cb * 32768;
        const uint32_t Bs = As + 16384;
#pragma unroll
        for (int ks = 0; ks < 4; ++ks) {
            uint32_t af[4][4];
#pragma unroll
            for (int mt = 0; mt < 4; ++mt) {
                uint32_t addr = As + sw128((uint32_t)(a_row + mt * 16) * 128 +
                                           (uint32_t)(a_c16 + ks * 2) * 16);
                asm volatile("ldmatrix.sync.aligned.m8n8.x4.shared.b16 {%0,%1,%2,%3}, [%4];"
                             : "=r"(af[mt][0]), "=r"(af[mt][1]), "=r"(af[mt][2]), "=r"(af[mt][3])
                             : "r"(addr));
            }
            uint32_t bf[4][2];
#pragma unroll
            for (int nt = 0; nt < 4; ++nt) {
                uint32_t addr = Bs + sw128((uint32_t)(b_row + nt * 8) * 128 +
                                           (uint32_t)(b_c16 + ks * 2) * 16);
                asm volatile("ldmatrix.sync.aligned.m8n8.x2.shared.b16 {%0,%1}, [%2];"
                             : "=r"(bf[nt][0]), "=r"(bf[nt][1])
                             : "r"(addr));
            }
#pragma unroll
            for (int mt = 0; mt < 4; ++mt)
#pragma unroll
                for (int nt = 0; nt < 4; ++nt)
                    asm volatile(
                        "mma.sync.aligned.m16n8k16.row.col.f32.bf16.bf16.f32 "
                        "{%0,%1,%2,%3}, {%4,%5,%6,%7}, {%8,%9}, {%0,%1,%2,%3};"
                        : "+f"(acc[mt][nt][0]), "+f"(acc[mt][nt][1]),
                          "+f"(acc[mt][nt][2]), "+f"(acc[mt][nt][3])
                        : "r"(af[mt][0]), "r"(af[mt][1]), "r"(af[mt][2]), "r"(af[mt][3]),
                          "r"(bf[nt][0]), "r"(bf[nt][1]));
        }
        __syncthreads();
    }

    // epilogue: direct stores
    float* __restrict__ out = nsel ? g_q : g_p;
    const int colb = wn * 32 + (lane & 3) * 2;
    const int rowb = m0 + wm * 64 + (lane >> 2);
#pragma unroll
    for (int mt = 0; mt < 4; ++mt) {
        int r0 = rowb + mt * 16;
        int r1 = r0 + 8;
#pragma unroll
        for (int nt = 0; nt < 4; ++nt) {
            int col = colb + nt * 8;
            if (r0 < N_NODES) {
                float2 v; v.x = acc[mt][nt][0]; v.y = acc[mt][nt][1];
                *(float2*)(out + (size_t)r0 * HID + col) = v;
            }
            if (r1 < N_NODES) {
                float2 v; v.x = acc[mt][nt][2]; v.y = acc[mt][nt][3];
                *(float2*)(out + (size_t)r1 * HID + col) = v;
            }
        }
    }
}

// ---------------- fused aggregation + bias + BN + ReLU (+ hi/lo split or final head) ----------------
__global__ __launch_bounds__(256) void k_agg(const float* __restrict__ bl,
                                             const float* __restrict__ gam,
                                             const float* __restrict__ bet,
                                             const float* __restrict__ rm,
                                             const float* __restrict__ rv,
                                             const float* __restrict__ lin_w,
                                             const float* __restrict__ lin_b,
                                             float* __restrict__ out,
                                             int last) {
    int node = (blockIdx.x * blockDim.x + threadIdx.x) >> 5;
    if (node >= N_NODES) return;
    int lane = threadIdx.x & 31;
    int c = lane * 4;

    int s0 = g_rowptr[node];
    int s1 = g_rowptr[node + 1];
    float4 acc = make_float4(0.f, 0.f, 0.f, 0.f);
    for (int e = s0; e < s1; ++e) {
        int s = g_srcs[e];
        float4 v = *(const float4*)(g_p + (size_t)s * HID + c);
        acc.x += v.x; acc.y += v.y; acc.z += v.z; acc.w += v.w;
    }
    float inv = 1.f / (float)max(s1 - s0, 1);

    float4 q   = *(const float4*)(g_q + (size_t)node * HID + c);
    float4 vb  = *(const float4*)(bl + c);
    float4 vg  = *(const float4*)(gam + c);
    float4 vbe = *(const float4*)(bet + c);
    float4 vrm = *(const float4*)(rm + c);
    float4 vrv = *(const float4*)(rv + c);

    float o0 = acc.x * inv + q.x + vb.x;
    float o1 = acc.y * inv + q.y + vb.y;
    float o2 = acc.z * inv + q.z + vb.z;
    float o3 = acc.w * inv + q.w + vb.w;

    o0 = (o0 - vrm.x) * (vg.x * rsqrtf(vrv.x + BN_EPS)) + vbe.x;
    o1 = (o1 - vrm.y) * (vg.y * rsqrtf(vrv.y + BN_EPS)) + vbe.y;
    o2 = (o2 - vrm.z) * (vg.z * rsqrtf(vrv.z + BN_EPS)) + vbe.z;
    o3 = (o3 - vrm.w) * (vg.w * rsqrtf(vrv.w + BN_EPS)) + vbe.w;

    o0 = fmaxf(o0, 0.f); o1 = fmaxf(o1, 0.f);
    o2 = fmaxf(o2, 0.f); o3 = fmaxf(o3, 0.f);

    if (last) {
        float4 wv = *(const float4*)(lin_w + c);
        float s = o0 * wv.x + o1 * wv.y + o2 * wv.z + o3 * wv.w;
#pragma unroll
        for (int off = 16; off > 0; off >>= 1)
            s += __shfl_down_sync(0xffffffffu, s, off);
        if (lane == 0) out[node] = s + lin_b[0];
    } else {
        uint32_t h0, l0, h1, l1;
        split2(o0, o1, h0, l0);
        split2(o2, o3, h1, l1);
        uint2 hv; hv.x = h0; hv.y = h1;
        uint2 lv; lv.x = l0; lv.y = l1;
        *(uint2*)((char*)g_ahi + ((size_t)node * 128 + c) * 2) = hv;
        *(uint2*)((char*)g_alo + ((size_t)node * 128 + c) * 2) = lv;
    }
}

// ---------------- launch ----------------
extern "C" void kernel_launch(void* const* d_in, const int* in_sizes, int n_in,
                              void* d_out, int out_size) {
    const float* x  = (const float*)d_in[0];
    const int*   ei = (const int*)d_in[1];
    const float* wl[3]; const float* wr[3]; const float* bl[3];
    const float* gm[3]; const float* be[3]; const float* rm[3]; const float* rv[3];
    for (int i = 0; i < 3; ++i) {
        const int base = 2 + 7 * i;
        wl[i] = (const float*)d_in[base + 0];
        wr[i] = (const float*)d_in[base + 1];
        bl[i] = (const float*)d_in[base + 2];
        gm[i] = (const float*)d_in[base + 3];
        be[i] = (const float*)d_in[base + 4];
        rm[i] = (const float*)d_in[base + 5];
        rv[i] = (const float*)d_in[base + 6];
    }
    const float* lin_w = (const float*)d_in[23];
    const float* lin_b = (const float*)d_in[24];
    float* out = (float*)d_out;

    cudaFuncSetAttribute(k_mma, cudaFuncAttributeMaxDynamicSharedMemorySize, 65536);

    const int TB = 256;
    const int nb_nodes = (N_NODES + TB - 1) / TB;
    const int nb_edges = (N_EDGES + TB - 1) / TB;
    const int nb_warps = (N_NODES * 32 + TB - 1) / TB;

    // CSR build
    k_zero_deg<<<nb_nodes, TB>>>();
    k_hist<<<nb_edges, TB>>>(ei);
    k_scan<<<1, 1024>>>();
    k_cursor_init<<<nb_nodes, TB>>>();
    k_place<<<nb_edges, TB>>>(ei);

    dim3 ggrid(N_TILES, 2);
    // layer 0 (K=160, pad 192)
    k_prep_x<<<(N_NODES * 48 + TB - 1) / TB, TB>>>(x);
    k_prep_w<<<(256 * 48 + TB - 1) / TB, TB>>>(wl[0], wr[0], 160, 192);
    k_mma<<<ggrid, 256, 65536>>>(192, 3);
    k_agg<<<nb_warps, TB>>>(bl[0], gm[0], be[0], rm[0], rv[0], lin_w, lin_b, out, 0);
    // layer 1 (K=128)
    k_prep_w<<<(256 * 32 + TB - 1) / TB, TB>>>(wl[1], wr[1], 128, 128);
    k_mma<<<ggrid, 256, 65536>>>(128, 2);
    k_agg<<<nb_warps, TB>>>(bl[1], gm[1], be[1], rm[1], rv[1], lin_w, lin_b, out, 0);
    // layer 2 (K=128)
    k_prep_w<<<(256 * 32 + TB - 1) / TB, TB>>>(wl[2], wr[2], 128, 128);
    k_mma<<<ggrid, 256, 65536>>>(128, 2);
    k_agg<<<nb_warps, TB>>>(bl[2], gm[2], be[2], rm[2], rv[2], lin_w, lin_b, out, 1);
}

// round 8
// speedup vs baseline: 1.9794x; 1.1312x over previous
#include <cuda_runtime.h>
#include <cuda_bf16.h>
#include <math.h>
#include <stdint.h>

#define N_NODES 100000
#define N_EDGES 1600000
#define HID 128
#define BN_EPS 1e-5f
#define N_TILES ((N_NODES + 127) / 128)   // 782

// ---------------- device scratch ----------------
__device__ __align__(16) float g_p[(size_t)N_NODES * HID];   // p = h@wl  (gather target)
__device__ __align__(16) float g_q[(size_t)N_NODES * HID];   // q = h@wr
__device__ __align__(16) __nv_bfloat16 g_ahi[(size_t)N_NODES * 192];  // activation hi
__device__ __align__(16) __nv_bfloat16 g_alo[(size_t)N_NODES * 192];  // activation lo
__device__ __align__(16) __nv_bfloat16 g_bhi[256 * 192];     // weight^T hi  [n][k]
__device__ __align__(16) __nv_bfloat16 g_blo[256 * 192];     // weight^T lo
__device__ int g_rowptr[N_NODES + 1];
__device__ int g_cursor[N_NODES];
__device__ int g_srcs[N_EDGES];

static __device__ __forceinline__ uint32_t sw128(uint32_t b) { return b ^ ((b >> 3) & 0x70u); }
__device__ __forceinline__ uint32_t smem_to_u32(const void* p) {
    uint32_t a;
    asm("{ .reg .u64 t; cvta.to.shared.u64 t, %1; cvt.u32.u64 %0, t; }" : "=r"(a) : "l"(p));
    return a;
}

// ---------------- CSR build ----------------
__global__ void k_zero_deg() {
    int i = blockIdx.x * blockDim.x + threadIdx.x;
    if (i < N_NODES) g_cursor[i] = 0;
}
__global__ void k_hist(const int* __restrict__ ei) {
    int e = blockIdx.x * blockDim.x + threadIdx.x;
    if (e < N_EDGES) {
        int dst = ei[N_EDGES + e];
        if (dst >= 0 && dst < N_NODES) atomicAdd(&g_cursor[dst], 1);
    }
}
__global__ void k_scan() {
    __shared__ int sums[1024];
    const int CH = (N_NODES + 1023) / 1024;
    int t = threadIdx.x;
    int lo = t * CH, hi = min(lo + CH, N_NODES);
    int s = 0;
    for (int i = lo; i < hi; ++i) s += g_cursor[i];
    sums[t] = s;
    __syncthreads();
    for (int off = 1; off < 1024; off <<= 1) {
        int v = (t >= off) ? sums[t - off] : 0;
        __syncthreads();
        sums[t] += v;
        __syncthreads();
    }
    int run = (t == 0) ? 0 : sums[t - 1];
    for (int i = lo; i < hi; ++i) {
        int d = g_cursor[i];
        g_rowptr[i] = run;
        run += d;
    }
    if (t == 1023) g_rowptr[N_NODES] = sums[1023];
}
__global__ void k_cursor_init() {
    int i = blockIdx.x * blockDim.x + threadIdx.x;
    if (i < N_NODES) g_cursor[i] = g_rowptr[i];
}
__global__ void k_place(const int* __restrict__ ei) {
    int e = blockIdx.x * blockDim.x + threadIdx.x;
    if (e < N_EDGES) {
        int src = ei[e];
        int dst = ei[N_EDGES + e];
        if (dst >= 0 && dst < N_NODES && src >= 0 && src < N_NODES) {
            int pos = atomicAdd(&g_cursor[dst], 1);
            if (pos >= 0 && pos < N_EDGES) g_srcs[pos] = src;
        }
    }
}

// ---------------- bf16 hi/lo split ----------------
__device__ __forceinline__ void split2(float f0, float f1, uint32_t& hp, uint32_t& lp) {
    asm("cvt.rn.bf16x2.f32 %0, %1, %2;" : "=r"(hp) : "f"(f1), "f"(f0));
    float h0 = __uint_as_float(hp << 16);
    float h1 = __uint_as_float(hp & 0xFFFF0000u);
    float l0 = f0 - h0, l1 = f1 - h1;
    asm("cvt.rn.bf16x2.f32 %0, %1, %2;" : "=r"(lp) : "f"(l1), "f"(l0));
}

// ---------------- prepass: x (fp32, K=160) -> g_ahi/g_alo (stride 192, zero-padded) ----------------
__global__ void k_prep_x(const float* __restrict__ x) {
    int idx = blockIdx.x * blockDim.x + threadIdx.x;
    if (idx >= N_NODES * 48) return;
    int row = idx / 48;
    int c = (idx % 48) * 4;
    float4 v = make_float4(0.f, 0.f, 0.f, 0.f);
    if (c < 160) v = *(const float4*)(x + (size_t)row * 160 + c);
    uint32_t h0, l0, h1, l1;
    split2(v.x, v.y, h0, l0);
    split2(v.z, v.w, h1, l1);
    uint32_t* ph = (uint32_t*)((char*)g_ahi + ((size_t)row * 192 + c) * 2);
    uint32_t* pl = (uint32_t*)((char*)g_alo + ((size_t)row * 192 + c) * 2);
    ph[0] = h0; ph[1] = h1;
    pl[0] = l0; pl[1] = l1;
}

// ---------------- prepass: weights [K,128]x2 -> g_bhi/g_blo transposed [256 x Kpad] ----------------
__global__ void k_prep_w(const float* __restrict__ wl, const float* __restrict__ wr,
                         int K, int Kpad) {
    int idx = blockIdx.x * blockDim.x + threadIdx.x;
    int total = 256 * (Kpad / 4);
    if (idx >= total) return;
    int n = idx / (Kpad / 4);
    int k = (idx % (Kpad / 4)) * 4;
    const float* W = (n < 128) ? wl : wr;
    int nc = n & 127;
    float f[4];
#pragma unroll
    for (int j = 0; j < 4; ++j)
        f[j] = (k + j < K) ? W[(size_t)(k + j) * 128 + nc] : 0.f;
    uint32_t h0, l0, h1, l1;
    split2(f[0], f[1], h0, l0);
    split2(f[2], f[3], h1, l1);
    uint32_t* ph = (uint32_t*)((char*)g_bhi + ((size_t)n * Kpad + k) * 2);
    uint32_t* pl = (uint32_t*)((char*)g_blo + ((size_t)n * Kpad + k) * 2);
    ph[0] = h0; ph[1] = h1;
    pl[0] = l0; pl[1] = l1;
}

// ---------------- tensor GEMM via mma.sync, cp.async double-buffered pipeline ----------------
__global__ __launch_bounds__(256, 2) void k_mma(int stride, int nkc) {
    extern __shared__ __align__(1024) char sm[];
    const uint32_t smb = smem_to_u32(sm);

    const int tid = threadIdx.x;
    const int lane = tid & 31;
    const int wid = tid >> 5;
    const int wm = wid & 1;
    const int wn = wid >> 1;
    const int m0 = blockIdx.x * 128;
    const int nsel = blockIdx.y;
    const int total = 3 * nkc;

    float acc[4][4][4];
#pragma unroll
    for (int i = 0; i < 4; ++i)
#pragma unroll
        for (int j = 0; j < 4; ++j)
#pragma unroll
            for (int r = 0; r < 4; ++r) acc[i][j][r] = 0.f;

    const int a_row = wm * 64 + ((lane >> 3) & 1) * 8 + (lane & 7);
    const int a_c16 = lane >> 4;
    const int b_row = wn * 32 + (lane & 7);
    const int b_c16 = (lane >> 3) & 1;

    auto stage = [&](int ci, int buf) {
        int t = ci / nkc;
        int kc = ci - t * nkc;
        const char* Aarr = (const char*)((t < 2) ? g_ahi : g_alo);
        const char* Barr = (const char*)((t == 1) ? g_blo : g_bhi);
        int k0 = kc * 64;
        uint32_t Ab = smb + buf * 32768;
        uint32_t Bb = Ab + 16384;
#pragma unroll
        for (int it = 0; it < 4; ++it) {
            int idx = tid + it * 256;
            int row = idx >> 3, c16 = idx & 7;
            int grow = m0 + row;
            const char* src = Aarr + ((size_t)grow * stride + k0) * 2 + c16 * 16;
            uint32_t dst = Ab + sw128(row * 128 + c16 * 16);
            int zf = (grow < N_NODES) ? 16 : 0;
            asm volatile("cp.async.cg.shared.global [%0], [%1], 16, %2;"
                         :: "r"(dst), "l"(src), "r"(zf));
        }
#pragma unroll
        for (int it = 0; it < 4; ++it) {
            int idx = tid + it * 256;
            int row = idx >> 3, c16 = idx & 7;
            const char* src = Barr + ((size_t)(nsel * 128 + row) * stride + k0) * 2 + c16 * 16;
            uint32_t dst = Bb + sw128(row * 128 + c16 * 16);
            asm volatile("cp.async.cg.shared.global [%0], [%1], 16;"
                         :: "r"(dst), "l"(src));
        }
        asm volatile("cp.async.commit_group;" ::: "memory");
    };

    stage(0, 0);
    for (int ci = 0; ci < total; ++ci) {
        int cb = ci & 1;
        if (ci + 1 < total) {
            stage(ci + 1, cb ^ 1);
            asm volatile("cp.async.wait_group 1;" ::: "memory");
        } else {
            asm volatile("cp.async.wait_group 0;" ::: "memory");
        }
        __syncthreads();

        const uint32_t As = smb + cb * 32768;
        const uint32_t Bs = As + 16384;
#pragma unroll
        for (int ks = 0; ks < 4; ++ks) {
            uint32_t af[4][4];
#pragma unroll
            for (int mt = 0; mt < 4; ++mt) {
                uint32_t addr = As + sw128((uint32_t)(a_row + mt * 16) * 128 +
                                           (uint32_t)(a_c16 + ks * 2) * 16);
                asm volatile("ldmatrix.sync.aligned.m8n8.x4.shared.b16 {%0,%1,%2,%3}, [%4];"
                             : "=r"(af[mt][0]), "=r"(af[mt][1]), "=r"(af[mt][2]), "=r"(af[mt][3])
                             : "r"(addr));
            }
            uint32_t bf[4][2];
#pragma unroll
            for (int nt = 0; nt < 4; ++nt) {
                uint32_t addr = Bs + sw128((uint32_t)(b_row + nt * 8) * 128 +
                                           (uint32_t)(b_c16 + ks * 2) * 16);
                asm volatile("ldmatrix.sync.aligned.m8n8.x2.shared.b16 {%0,%1}, [%2];"
                             : "=r"(bf[nt][0]), "=r"(bf[nt][1])
                             : "r"(addr));
            }
#pragma unroll
            for (int mt = 0; mt < 4; ++mt)
#pragma unroll
                for (int nt = 0; nt < 4; ++nt)
                    asm volatile(
                        "mma.sync.aligned.m16n8k16.row.col.f32.bf16.bf16.f32 "
                        "{%0,%1,%2,%3}, {%4,%5,%6,%7}, {%8,%9}, {%0,%1,%2,%3};"
                        : "+f"(acc[mt][nt][0]), "+f"(acc[mt][nt][1]),
                          "+f"(acc[mt][nt][2]), "+f"(acc[mt][nt][3])
                        : "r"(af[mt][0]), "r"(af[mt][1]), "r"(af[mt][2]), "r"(af[mt][3]),
                          "r"(bf[nt][0]), "r"(bf[nt][1]));
        }
        __syncthreads();
    }

    float* __restrict__ out = nsel ? g_q : g_p;
    const int colb = wn * 32 + (lane & 3) * 2;
    const int rowb = m0 + wm * 64 + (lane >> 2);
#pragma unroll
    for (int mt = 0; mt < 4; ++mt) {
        int r0 = rowb + mt * 16;
        int r1 = r0 + 8;
#pragma unroll
        for (int nt = 0; nt < 4; ++nt) {
            int col = colb + nt * 8;
            if (r0 < N_NODES) {
                float2 v; v.x = acc[mt][nt][0]; v.y = acc[mt][nt][1];
                *(float2*)(out + (size_t)r0 * HID + col) = v;
            }
            if (r1 < N_NODES) {
                float2 v; v.x = acc[mt][nt][2]; v.y = acc[mt][nt][3];
                *(float2*)(out + (size_t)r1 * HID + col) = v;
            }
        }
    }
}

// ---------------- fused aggregation + bias + BN + ReLU (+ hi/lo split or final head) ----------------
__global__ __launch_bounds__(256) void k_agg(const float* __restrict__ bl,
                                             const float* __restrict__ gam,
                                             const float* __restrict__ bet,
                                             const float* __restrict__ rm,
                                             const float* __restrict__ rv,
                                             const float* __restrict__ lin_w,
                                             const float* __restrict__ lin_b,
                                             float* __restrict__ out,
                                             int last) {
    int node = (blockIdx.x * blockDim.x + threadIdx.x) >> 5;
    if (node >= N_NODES) return;
    int lane = threadIdx.x & 31;
    int c = lane * 4;

    int s0 = g_rowptr[node];
    int s1 = g_rowptr[node + 1];
    float4 acc = make_float4(0.f, 0.f, 0.f, 0.f);
    int e = s0;
    // 4-wide software pipeline: 4 independent gathers in flight
    for (; e + 4 <= s1; e += 4) {
        int i0 = g_srcs[e + 0];
        int i1 = g_srcs[e + 1];
        int i2 = g_srcs[e + 2];
        int i3 = g_srcs[e + 3];
        float4 v0 = *(const float4*)(g_p + (size_t)i0 * HID + c);
        float4 v1 = *(const float4*)(g_p + (size_t)i1 * HID + c);
        float4 v2 = *(const float4*)(g_p + (size_t)i2 * HID + c);
        float4 v3 = *(const float4*)(g_p + (size_t)i3 * HID + c);
        acc.x += v0.x + v1.x + v2.x + v3.x;
        acc.y += v0.y + v1.y + v2.y + v3.y;
        acc.z += v0.z + v1.z + v2.z + v3.z;
        acc.w += v0.w + v1.w + v2.w + v3.w;
    }
    for (; e < s1; ++e) {
        int s = g_srcs[e];
        float4 v = *(const float4*)(g_p + (size_t)s * HID + c);
        acc.x += v.x; acc.y += v.y; acc.z += v.z; acc.w += v.w;
    }
    float inv = 1.f / (float)max(s1 - s0, 1);

    float4 q   = *(const float4*)(g_q + (size_t)node * HID + c);
    float4 vb  = *(const float4*)(bl + c);
    float4 vg  = *(const float4*)(gam + c);
    float4 vbe = *(const float4*)(bet + c);
    float4 vrm = *(const float4*)(rm + c);
    float4 vrv = *(const float4*)(rv + c);

    float o0 = acc.x * inv + q.x + vb.x;
    float o1 = acc.y * inv + q.y + vb.y;
    float o2 = acc.z * inv + q.z + vb.z;
    float o3 = acc.w * inv + q.w + vb.w;

    o0 = (o0 - vrm.x) * (vg.x * rsqrtf(vrv.x + BN_EPS)) + vbe.x;
    o1 = (o1 - vrm.y) * (vg.y * rsqrtf(vrv.y + BN_EPS)) + vbe.y;
    o2 = (o2 - vrm.z) * (vg.z * rsqrtf(vrv.z + BN_EPS)) + vbe.z;
    o3 = (o3 - vrm.w) * (vg.w * rsqrtf(vrv.w + BN_EPS)) + vbe.w;

    o0 = fmaxf(o0, 0.f); o1 = fmaxf(o1, 0.f);
    o2 = fmaxf(o2, 0.f); o3 = fmaxf(o3, 0.f);

    if (last) {
        float4 wv = *(const float4*)(lin_w + c);
        float s = o0 * wv.x + o1 * wv.y + o2 * wv.z + o3 * wv.w;
#pragma unroll
        for (int off = 16; off > 0; off >>= 1)
            s += __shfl_down_sync(0xffffffffu, s, off);
        if (lane == 0) out[node] = s + lin_b[0];
    } else {
        uint32_t h0, l0, h1, l1;
        split2(o0, o1, h0, l0);
        split2(o2, o3, h1, l1);
        uint2 hv; hv.x = h0; hv.y = h1;
        uint2 lv; lv.x = l0; lv.y = l1;
        *(uint2*)((char*)g_ahi + ((size_t)node * 128 + c) * 2) = hv;
        *(uint2*)((char*)g_alo + ((size_t)node * 128 + c) * 2) = lv;
    }
}

// ---------------- launch ----------------
extern "C" void kernel_launch(void* const* d_in, const int* in_sizes, int n_in,
                              void* d_out, int out_size) {
    const float* x  = (const float*)d_in[0];
    const int*   ei = (const int*)d_in[1];
    const float* wl[3]; const float* wr[3]; const float* bl[3];
    const float* gm[3]; const float* be[3]; const float* rm[3]; const float* rv[3];
    for (int i = 0; i < 3; ++i) {
        const int base = 2 + 7 * i;
        wl[i] = (const float*)d_in[base + 0];
        wr[i] = (const float*)d_in[base + 1];
        bl[i] = (const float*)d_in[base + 2];
        gm[i] = (const float*)d_in[base + 3];
        be[i] = (const float*)d_in[base + 4];
        rm[i] = (const float*)d_in[base + 5];
        rv[i] = (const float*)d_in[base + 6];
    }
    const float* lin_w = (const float*)d_in[23];
    const float* lin_b = (const float*)d_in[24];
    float* out = (float*)d_out;

    cudaFuncSetAttribute(k_mma, cudaFuncAttributeMaxDynamicSharedMemorySize, 65536);

    const int TB = 256;
    const int nb_nodes = (N_NODES + TB - 1) / TB;
    const int nb_edges = (N_EDGES + TB - 1) / TB;
    const int nb_warps = (N_NODES * 32 + TB - 1) / TB;

    // fork: CSR build runs concurrently with layer-0 prep + GEMM.
    // (streams/events intentionally not destroyed: host-side objects only,
    //  kernel_launch is invoked a handful of times; destroying during active
    //  capture risks invalidating it)
    cudaStream_t s2;
    cudaStreamCreateWithFlags(&s2, cudaStreamNonBlocking);
    cudaEvent_t eFork, eJoin;
    cudaEventCreateWithFlags(&eFork, cudaEventDisableTiming);
    cudaEventCreateWithFlags(&eJoin, cudaEventDisableTiming);

    cudaEventRecord(eFork, 0);
    cudaStreamWaitEvent(s2, eFork, 0);

    // CSR build on side stream
    k_zero_deg<<<nb_nodes, TB, 0, s2>>>();
    k_hist<<<nb_edges, TB, 0, s2>>>(ei);
    k_scan<<<1, 1024, 0, s2>>>();
    k_cursor_init<<<nb_nodes, TB, 0, s2>>>();
    k_place<<<nb_edges, TB, 0, s2>>>(ei);
    cudaEventRecord(eJoin, s2);

    dim3 ggrid(N_TILES, 2);
    // main stream: layer-0 prep + GEMM (independent of CSR)
    k_prep_x<<<(N_NODES * 48 + TB - 1) / TB, TB>>>(x);
    k_prep_w<<<(256 * 48 + TB - 1) / TB, TB>>>(wl[0], wr[0], 160, 192);
    k_mma<<<ggrid, 256, 65536>>>(192, 3);

    // join: agg needs CSR
    cudaStreamWaitEvent(0, eJoin, 0);
    k_agg<<<nb_warps, TB>>>(bl[0], gm[0], be[0], rm[0], rv[0], lin_w, lin_b, out, 0);
    // layer 1
    k_prep_w<<<(256 * 32 + TB - 1) / TB, TB>>>(wl[1], wr[1], 128, 128);
    k_mma<<<ggrid, 256, 65536>>>(128, 2);
    k_agg<<<nb_warps, TB>>>(bl[1], gm[1], be[1], rm[1], rv[1], lin_w, lin_b, out, 0);
    // layer 2
    k_prep_w<<<(256 * 32 + TB - 1) / TB, TB>>>(wl[2], wr[2], 128, 128);
    k_mma<<<ggrid, 256, 65536>>>(128, 2);
    k_agg<<<nb_warps, TB>>>(bl[2], gm[2], be[2], rm[2], rv[2], lin_w, lin_b, out, 1);
}

// round 10
// speedup vs baseline: 2.2028x; 1.1129x over previous
#include <cuda_runtime.h>
#include <cuda_bf16.h>
#include <cuda_fp16.h>
#include <math.h>
#include <stdint.h>

#define N_NODES 100000
#define N_EDGES 1600000
#define HID 128
#define BN_EPS 1e-5f
#define N_TILES ((N_NODES + 127) / 128)   // 782

// ---------------- device scratch ----------------
__device__ __align__(16) __half g_ph[(size_t)N_NODES * HID];  // p = h@wl, fp16 (gather target)
__device__ __align__(16) float g_q[(size_t)N_NODES * HID];    // q = h@wr, fp32
__device__ __align__(16) __nv_bfloat16 g_ahi[(size_t)N_NODES * 192];  // activation hi
__device__ __align__(16) __nv_bfloat16 g_alo[(size_t)N_NODES * 192];  // activation lo
__device__ __align__(16) __nv_bfloat16 g_bhi[256 * 192];     // weight^T hi  [n][k]
__device__ __align__(16) __nv_bfloat16 g_blo[256 * 192];     // weight^T lo
__device__ int g_rowptr[N_NODES + 1];
__device__ int g_cursor[N_NODES];
__device__ int g_srcs[N_EDGES];

static __device__ __forceinline__ uint32_t sw128(uint32_t b) { return b ^ ((b >> 3) & 0x70u); }
__device__ __forceinline__ uint32_t smem_to_u32(const void* p) {
    uint32_t a;
    asm("{ .reg .u64 t; cvta.to.shared.u64 t, %1; cvt.u32.u64 %0, t; }" : "=r"(a) : "l"(p));
    return a;
}

// ---------------- CSR build ----------------
__global__ void k_zero_deg() {
    int i = blockIdx.x * blockDim.x + threadIdx.x;
    if (i < N_NODES) g_cursor[i] = 0;
}
__global__ void k_hist(const int* __restrict__ ei) {
    int e = blockIdx.x * blockDim.x + threadIdx.x;
    if (e < N_EDGES) {
        int dst = ei[N_EDGES + e];
        if (dst >= 0 && dst < N_NODES) atomicAdd(&g_cursor[dst], 1);
    }
}
__global__ void k_scan() {
    __shared__ int sums[1024];
    const int CH = (N_NODES + 1023) / 1024;
    int t = threadIdx.x;
    int lo = t * CH, hi = min(lo + CH, N_NODES);
    int s = 0;
    for (int i = lo; i < hi; ++i) s += g_cursor[i];
    sums[t] = s;
    __syncthreads();
    for (int off = 1; off < 1024; off <<= 1) {
        int v = (t >= off) ? sums[t - off] : 0;
        __syncthreads();
        sums[t] += v;
        __syncthreads();
    }
    int run = (t == 0) ? 0 : sums[t - 1];
    for (int i = lo; i < hi; ++i) {
        int d = g_cursor[i];
        g_rowptr[i] = run;
        run += d;
    }
    if (t == 1023) g_rowptr[N_NODES] = sums[1023];
}
__global__ void k_cursor_init() {
    int i = blockIdx.x * blockDim.x + threadIdx.x;
    if (i < N_NODES) g_cursor[i] = g_rowptr[i];
}
__global__ void k_place(const int* __restrict__ ei) {
    int e = blockIdx.x * blockDim.x + threadIdx.x;
    if (e < N_EDGES) {
        int src = ei[e];
        int dst = ei[N_EDGES + e];
        if (dst >= 0 && dst < N_NODES && src >= 0 && src < N_NODES) {
            int pos = atomicAdd(&g_cursor[dst], 1);
            if (pos >= 0 && pos < N_EDGES) g_srcs[pos] = src;
        }
    }
}

// ---------------- bf16 hi/lo split ----------------
__device__ __forceinline__ void split2(float f0, float f1, uint32_t& hp, uint32_t& lp) {
    asm("cvt.rn.bf16x2.f32 %0, %1, %2;" : "=r"(hp) : "f"(f1), "f"(f0));
    float h0 = __uint_as_float(hp << 16);
    float h1 = __uint_as_float(hp & 0xFFFF0000u);
    float l0 = f0 - h0, l1 = f1 - h1;
    asm("cvt.rn.bf16x2.f32 %0, %1, %2;" : "=r"(lp) : "f"(l1), "f"(l0));
}

// ---------------- prepass: x (fp32, K=160) -> g_ahi/g_alo (stride 192, zero-padded) ----------------
__global__ void k_prep_x(const float* __restrict__ x) {
    int idx = blockIdx.x * blockDim.x + threadIdx.x;
    if (idx >= N_NODES * 48) return;
    int row = idx / 48;
    int c = (idx % 48) * 4;
    float4 v = make_float4(0.f, 0.f, 0.f, 0.f);
    if (c < 160) v = *(const float4*)(x + (size_t)row * 160 + c);
    uint32_t h0, l0, h1, l1;
    split2(v.x, v.y, h0, l0);
    split2(v.z, v.w, h1, l1);
    uint32_t* ph = (uint32_t*)((char*)g_ahi + ((size_t)row * 192 + c) * 2);
    uint32_t* pl = (uint32_t*)((char*)g_alo + ((size_t)row * 192 + c) * 2);
    ph[0] = h0; ph[1] = h1;
    pl[0] = l0; pl[1] = l1;
}

// ---------------- prepass: weights [K,128]x2 -> g_bhi/g_blo transposed [256 x Kpad] ----------------
__global__ void k_prep_w(const float* __restrict__ wl, const float* __restrict__ wr,
                         int K, int Kpad) {
    int idx = blockIdx.x * blockDim.x + threadIdx.x;
    int total = 256 * (Kpad / 4);
    if (idx >= total) return;
    int n = idx / (Kpad / 4);
    int k = (idx % (Kpad / 4)) * 4;
    const float* W = (n < 128) ? wl : wr;
    int nc = n & 127;
    float f[4];
#pragma unroll
    for (int j = 0; j < 4; ++j)
        f[j] = (k + j < K) ? W[(size_t)(k + j) * 128 + nc] : 0.f;
    uint32_t h0, l0, h1, l1;
    split2(f[0], f[1], h0, l0);
    split2(f[2], f[3], h1, l1);
    uint32_t* ph = (uint32_t*)((char*)g_bhi + ((size_t)n * Kpad + k) * 2);
    uint32_t* pl = (uint32_t*)((char*)g_blo + ((size_t)n * Kpad + k) * 2);
    ph[0] = h0; ph[1] = h1;
    pl[0] = l0; pl[1] = l1;
}

// ---------------- tensor GEMM via mma.sync, cp.async double-buffered pipeline ----------------
// blockIdx.y==0 -> p half (stored fp16 to g_ph), ==1 -> q half (fp32 to g_q)
__global__ __launch_bounds__(256, 2) void k_mma(int stride, int nkc) {
    extern __shared__ __align__(1024) char sm[];
    const uint32_t smb = smem_to_u32(sm);

    const int tid = threadIdx.x;
    const int lane = tid & 31;
    const int wid = tid >> 5;
    const int wm = wid & 1;
    const int wn = wid >> 1;
    const int m0 = blockIdx.x * 128;
    const int nsel = blockIdx.y;
    const int total = 3 * nkc;

    float acc[4][4][4];
#pragma unroll
    for (int i = 0; i < 4; ++i)
#pragma unroll
        for (int j = 0; j < 4; ++j)
#pragma unroll
            for (int r = 0; r < 4; ++r) acc[i][j][r] = 0.f;

    const int a_row = wm * 64 + ((lane >> 3) & 1) * 8 + (lane & 7);
    const int a_c16 = lane >> 4;
    const int b_row = wn * 32 + (lane & 7);
    const int b_c16 = (lane >> 3) & 1;

    auto stage = [&](int ci, int buf) {
        int t = ci / nkc;
        int kc = ci - t * nkc;
        const char* Aarr = (const char*)((t < 2) ? g_ahi : g_alo);
        const char* Barr = (const char*)((t == 1) ? g_blo : g_bhi);
        int k0 = kc * 64;
        uint32_t Ab = smb + buf * 32768;
        uint32_t Bb = Ab + 16384;
#pragma unroll
        for (int it = 0; it < 4; ++it) {
            int idx = tid + it * 256;
            int row = idx >> 3, c16 = idx & 7;
            int grow = m0 + row;
            const char* src = Aarr + ((size_t)grow * stride + k0) * 2 + c16 * 16;
            uint32_t dst = Ab + sw128(row * 128 + c16 * 16);
            int zf = (grow < N_NODES) ? 16 : 0;
            asm volatile("cp.async.cg.shared.global [%0], [%1], 16, %2;"
                         :: "r"(dst), "l"(src), "r"(zf));
        }
#pragma unroll
        for (int it = 0; it < 4; ++it) {
            int idx = tid + it * 256;
            int row = idx >> 3, c16 = idx & 7;
            const char* src = Barr + ((size_t)(nsel * 128 + row) * stride + k0) * 2 + c16 * 16;
            uint32_t dst = Bb + sw128(row * 128 + c16 * 16);
            asm volatile("cp.async.cg.shared.global [%0], [%1], 16;"
                         :: "r"(dst), "l"(src));
        }
        asm volatile("cp.async.commit_group;" ::: "memory");
    };

    stage(0, 0);
    for (int ci = 0; ci < total; ++ci) {
        int cb = ci & 1;
        if (ci + 1 < total) {
            stage(ci + 1, cb ^ 1);
            asm volatile("cp.async.wait_group 1;" ::: "memory");
        } else {
            asm volatile("cp.async.wait_group 0;" ::: "memory");
        }
        __syncthreads();

        const uint32_t As = smb + cb * 32768;
        const uint32_t Bs = As + 16384;
#pragma unroll
        for (int ks = 0; ks < 4; ++ks) {
            uint32_t af[4][4];
#pragma unroll
            for (int mt = 0; mt < 4; ++mt) {
                uint32_t addr = As + sw128((uint32_t)(a_row + mt * 16) * 128 +
                                           (uint32_t)(a_c16 + ks * 2) * 16);
                asm volatile("ldmatrix.sync.aligned.m8n8.x4.shared.b16 {%0,%1,%2,%3}, [%4];"
                             : "=r"(af[mt][0]), "=r"(af[mt][1]), "=r"(af[mt][2]), "=r"(af[mt][3])
                             : "r"(addr));
            }
            uint32_t bf[4][2];
#pragma unroll
            for (int nt = 0; nt < 4; ++nt) {
                uint32_t addr = Bs + sw128((uint32_t)(b_row + nt * 8) * 128 +
                                           (uint32_t)(b_c16 + ks * 2) * 16);
                asm volatile("ldmatrix.sync.aligned.m8n8.x2.shared.b16 {%0,%1}, [%2];"
                             : "=r"(bf[nt][0]), "=r"(bf[nt][1])
                             : "r"(addr));
            }
#pragma unroll
            for (int mt = 0; mt < 4; ++mt)
#pragma unroll
                for (int nt = 0; nt < 4; ++nt)
                    asm volatile(
                        "mma.sync.aligned.m16n8k16.row.col.f32.bf16.bf16.f32 "
                        "{%0,%1,%2,%3}, {%4,%5,%6,%7}, {%8,%9}, {%0,%1,%2,%3};"
                        : "+f"(acc[mt][nt][0]), "+f"(acc[mt][nt][1]),
                          "+f"(acc[mt][nt][2]), "+f"(acc[mt][nt][3])
                        : "r"(af[mt][0]), "r"(af[mt][1]), "r"(af[mt][2]), "r"(af[mt][3]),
                          "r"(bf[nt][0]), "r"(bf[nt][1]));
        }
        __syncthreads();
    }

    const int colb = wn * 32 + (lane & 3) * 2;
    const int rowb = m0 + wm * 64 + (lane >> 2);
    if (nsel == 0) {
        // p half: store fp16
#pragma unroll
        for (int mt = 0; mt < 4; ++mt) {
            int r0 = rowb + mt * 16;
            int r1 = r0 + 8;
#pragma unroll
            for (int nt = 0; nt < 4; ++nt) {
                int col = colb + nt * 8;
                if (r0 < N_NODES)
                    *(__half2*)(g_ph + (size_t)r0 * HID + col) =
                        __floats2half2_rn(acc[mt][nt][0], acc[mt][nt][1]);
                if (r1 < N_NODES)
                    *(__half2*)(g_ph + (size_t)r1 * HID + col) =
                        __floats2half2_rn(acc[mt][nt][2], acc[mt][nt][3]);
            }
        }
    } else {
        // q half: store fp32
#pragma unroll
        for (int mt = 0; mt < 4; ++mt) {
            int r0 = rowb + mt * 16;
            int r1 = r0 + 8;
#pragma unroll
            for (int nt = 0; nt < 4; ++nt) {
                int col = colb + nt * 8;
                if (r0 < N_NODES) {
                    float2 v; v.x = acc[mt][nt][0]; v.y = acc[mt][nt][1];
                    *(float2*)(g_q + (size_t)r0 * HID + col) = v;
                }
                if (r1 < N_NODES) {
                    float2 v; v.x = acc[mt][nt][2]; v.y = acc[mt][nt][3];
                    *(float2*)(g_q + (size_t)r1 * HID + col) = v;
                }
            }
        }
    }
}

// ---------------- fused aggregation + bias + BN + ReLU (+ hi/lo split or final head) ----------------
__global__ __launch_bounds__(256) void k_agg(const float* __restrict__ bl,
                                             const float* __restrict__ gam,
                                             const float* __restrict__ bet,
                                             const float* __restrict__ rm,
                                             const float* __restrict__ rv,
                                             const float* __restrict__ lin_w,
                                             const float* __restrict__ lin_b,
                                             float* __restrict__ out,
                                             int last) {
    int node = (blockIdx.x * blockDim.x + threadIdx.x) >> 5;
    if (node >= N_NODES) return;
    int lane = threadIdx.x & 31;
    int c = lane * 4;

    int s0 = g_rowptr[node];
    int s1 = g_rowptr[node + 1];
    float4 acc = make_float4(0.f, 0.f, 0.f, 0.f);
    int e = s0;
    // 4-wide software pipeline: 4 independent fp16 gathers (8B each) in flight
    for (; e + 4 <= s1; e += 4) {
        int i0 = g_srcs[e + 0];
        int i1 = g_srcs[e + 1];
        int i2 = g_srcs[e + 2];
        int i3 = g_srcs[e + 3];
        uint2 u0 = *(const uint2*)(g_ph + (size_t)i0 * HID + c);
        uint2 u1 = *(const uint2*)(g_ph + (size_t)i1 * HID + c);
        uint2 u2 = *(const uint2*)(g_ph + (size_t)i2 * HID + c);
        uint2 u3 = *(const uint2*)(g_ph + (size_t)i3 * HID + c);
#pragma unroll
        for (int j = 0; j < 1; ++j) { }  // keep loads batched
        float2 a0 = __half22float2(*(const __half2*)&u0.x);
        float2 b0 = __half22float2(*(const __half2*)&u0.y);
        float2 a1 = __half22float2(*(const __half2*)&u1.x);
        float2 b1 = __half22float2(*(const __half2*)&u1.y);
        float2 a2 = __half22float2(*(const __half2*)&u2.x);
        float2 b2 = __half22float2(*(const __half2*)&u2.y);
        float2 a3 = __half22float2(*(const __half2*)&u3.x);
        float2 b3 = __half22float2(*(const __half2*)&u3.y);
        acc.x += a0.x + a1.x + a2.x + a3.x;
        acc.y += a0.y + a1.y + a2.y + a3.y;
        acc.z += b0.x + b1.x + b2.x + b3.x;
        acc.w += b0.y + b1.y + b2.y + b3.y;
    }
    for (; e < s1; ++e) {
        int s = g_srcs[e];
        uint2 u = *(const uint2*)(g_ph + (size_t)s * HID + c);
        float2 a = __half22float2(*(const __half2*)&u.x);
        float2 b = __half22float2(*(const __half2*)&u.y);
        acc.x += a.x; acc.y += a.y; acc.z += b.x; acc.w += b.y;
    }
    float inv = 1.f / (float)max(s1 - s0, 1);

    float4 q   = *(const float4*)(g_q + (size_t)node * HID + c);
    float4 vb  = *(const float4*)(bl + c);
    float4 vg  = *(const float4*)(gam + c);
    float4 vbe = *(const float4*)(bet + c);
    float4 vrm = *(const float4*)(rm + c);
    float4 vrv = *(const float4*)(rv + c);

    float o0 = acc.x * inv + q.x + vb.x;
    float o1 = acc.y * inv + q.y + vb.y;
    float o2 = acc.z * inv + q.z + vb.z;
    float o3 = acc.w * inv + q.w + vb.w;

    o0 = (o0 - vrm.x) * (vg.x * rsqrtf(vrv.x + BN_EPS)) + vbe.x;
    o1 = (o1 - vrm.y) * (vg.y * rsqrtf(vrv.y + BN_EPS)) + vbe.y;
    o2 = (o2 - vrm.z) * (vg.z * rsqrtf(vrv.z + BN_EPS)) + vbe.z;
    o3 = (o3 - vrm.w) * (vg.w * rsqrtf(vrv.w + BN_EPS)) + vbe.w;

    o0 = fmaxf(o0, 0.f); o1 = fmaxf(o1, 0.f);
    o2 = fmaxf(o2, 0.f); o3 = fmaxf(o3, 0.f);

    if (last) {
        float4 wv = *(const float4*)(lin_w + c);
        float s = o0 * wv.x + o1 * wv.y + o2 * wv.z + o3 * wv.w;
#pragma unroll
        for (int off = 16; off > 0; off >>= 1)
            s += __shfl_down_sync(0xffffffffu, s, off);
        if (lane == 0) out[node] = s + lin_b[0];
    } else {
        uint32_t h0, l0, h1, l1;
        split2(o0, o1, h0, l0);
        split2(o2, o3, h1, l1);
        uint2 hv; hv.x = h0; hv.y = h1;
        uint2 lv; lv.x = l0; lv.y = l1;
        *(uint2*)((char*)g_ahi + ((size_t)node * 128 + c) * 2) = hv;
        *(uint2*)((char*)g_alo + ((size_t)node * 128 + c) * 2) = lv;
    }
}

// ---------------- launch ----------------
extern "C" void kernel_launch(void* const* d_in, const int* in_sizes, int n_in,
                              void* d_out, int out_size) {
    const float* x  = (const float*)d_in[0];
    const int*   ei = (const int*)d_in[1];
    const float* wl[3]; const float* wr[3]; const float* bl[3];
    const float* gm[3]; const float* be[3]; const float* rm[3]; const float* rv[3];
    for (int i = 0; i < 3; ++i) {
        const int base = 2 + 7 * i;
        wl[i] = (const float*)d_in[base + 0];
        wr[i] = (const float*)d_in[base + 1];
        bl[i] = (const float*)d_in[base + 2];
        gm[i] = (const float*)d_in[base + 3];
        be[i] = (const float*)d_in[base + 4];
        rm[i] = (const float*)d_in[base + 5];
        rv[i] = (const float*)d_in[base + 6];
    }
    const float* lin_w = (const float*)d_in[23];
    const float* lin_b = (const float*)d_in[24];
    float* out = (float*)d_out;

    cudaFuncSetAttribute(k_mma, cudaFuncAttributeMaxDynamicSharedMemorySize, 65536);

    const int TB = 256;
    const int nb_nodes = (N_NODES + TB - 1) / TB;
    const int nb_edges = (N_EDGES + TB - 1) / TB;
    const int nb_warps = (N_NODES * 32 + TB - 1) / TB;

    // fork: CSR build runs concurrently with layer-0 prep + GEMM.
    cudaStream_t s2;
    cudaStreamCreateWithFlags(&s2, cudaStreamNonBlocking);
    cudaEvent_t eFork, eJoin;
    cudaEventCreateWithFlags(&eFork, cudaEventDisableTiming);
    cudaEventCreateWithFlags(&eJoin, cudaEventDisableTiming);

    cudaEventRecord(eFork, 0);
    cudaStreamWaitEvent(s2, eFork, 0);

    k_zero_deg<<<nb_nodes, TB, 0, s2>>>();
    k_hist<<<nb_edges, TB, 0, s2>>>(ei);
    k_scan<<<1, 1024, 0, s2>>>();
    k_cursor_init<<<nb_nodes, TB, 0, s2>>>();
    k_place<<<nb_edges, TB, 0, s2>>>(ei);
    cudaEventRecord(eJoin, s2);

    dim3 ggrid(N_TILES, 2);
    k_prep_x<<<(N_NODES * 48 + TB - 1) / TB, TB>>>(x);
    k_prep_w<<<(256 * 48 + TB - 1) / TB, TB>>>(wl[0], wr[0], 160, 192);
    k_mma<<<ggrid, 256, 65536>>>(192, 3);

    cudaStreamWaitEvent(0, eJoin, 0);
    k_agg<<<nb_warps, TB>>>(bl[0], gm[0], be[0], rm[0], rv[0], lin_w, lin_b, out, 0);
    k_prep_w<<<(256 * 32 + TB - 1) / TB, TB>>>(wl[1], wr[1], 128, 128);
    k_mma<<<ggrid, 256, 65536>>>(128, 2);
    k_agg<<<nb_warps, TB>>>(bl[1], gm[1], be[1], rm[1], rv[1], lin_w, lin_b, out, 0);
    k_prep_w<<<(256 * 32 + TB - 1) / TB, TB>>>(wl[2], wr[2], 128, 128);
    k_mma<<<ggrid, 256, 65536>>>(128, 2);
    k_agg<<<nb_warps, TB>>>(bl[2], gm[2], be[2], rm[2], rv[2], lin_w, lin_b, out, 1);
}